// round 8
// baseline (speedup 1.0000x reference)
#include <cuda_runtime.h>
#include <cuda_fp16.h>
#include <cstdint>

#define D      128      // D_IN = D_OUT
#define NMAX   100000

// Scratch (device globals; no allocation allowed)
__device__ __half g_xh[NMAX * D];   // x rounded to fp16 (GEMM A operand)
__device__ __half g_yh[NMAX * D];   // y = x @ W2, stored fp16
// ============================================================================
// PTX helpers (base ISA: cp.async / ldmatrix / mma.sync)
// ============================================================================
__device__ __forceinline__ uint32_t smem_to_u32(const void* p) {
    uint32_t a;
    asm("{ .reg .u64 t; cvta.to.shared.u64 t, %1; cvt.u32.u64 %0, t; }"
        : "=r"(a) : "l"(p));
    return a;
}
#define CP_ASYNC16(dst, src, sz) \
    asm volatile("cp.async.cg.shared.global [%0], [%1], 16, %2;" \
        :: "r"(dst), "l"(src), "r"(sz))
#define CP_COMMIT() asm volatile("cp.async.commit_group;" ::: "memory")
#define CP_WAIT1()  asm volatile("cp.async.wait_group 1;"  ::: "memory")

#define LDSM_X4(r0,r1,r2,r3,addr) \
    asm volatile("ldmatrix.sync.aligned.m8n8.x4.shared.b16 {%0,%1,%2,%3}, [%4];" \
        : "=r"(r0), "=r"(r1), "=r"(r2), "=r"(r3) : "r"(addr))
#define LDSM_X4T(r0,r1,r2,r3,addr) \
    asm volatile("ldmatrix.sync.aligned.m8n8.x4.trans.shared.b16 {%0,%1,%2,%3}, [%4];" \
        : "=r"(r0), "=r"(r1), "=r"(r2), "=r"(r3) : "r"(addr))

// fp16 inputs, fp32 accumulate
#define MMA16816F16(c, a, b) \
    asm volatile("mma.sync.aligned.m16n8k16.row.col.f32.f16.f16.f32 " \
        "{%0,%1,%2,%3}, {%4,%5,%6,%7}, {%8,%9}, {%0,%1,%2,%3};" \
        : "+f"((c)[0]), "+f"((c)[1]), "+f"((c)[2]), "+f"((c)[3]) \
        : "r"((a)[0]), "r"((a)[1]), "r"((a)[2]), "r"((a)[3]), \
          "r"((b)[0]), "r"((b)[1]))

// ============================================================================
// Kernel 1: round x -> fp16 (one pass)
// ============================================================================
__global__ void convert_kernel(const float* __restrict__ x, int n4) {
    int i = blockIdx.x * blockDim.x + threadIdx.x;
    if (i >= n4) return;
    float4 v = reinterpret_cast<const float4*>(x)[i];
    __half2 h0 = __floats2half2_rn(v.x, v.y);
    __half2 h1 = __floats2half2_rn(v.z, v.w);
    reinterpret_cast<uint2*>(g_xh)[i] =
        make_uint2(*(uint32_t*)&h0, *(uint32_t*)&h1);
}

// ============================================================================
// Kernel 2: persistent GEMM via mma.sync, 2-term fp16 split (W split hi/lo)
//   (m_tile, nh): nh=0 -> d_out = x@W1 + b (fp32) ; nh=1 -> g_yh = x@W2 (fp16)
//   CTA tile 128(M) x 128(N), K=128. 8 warps, warp tile 32M x 64N.
//   SMEM: A fp16 double-buffered (2 x 32KB) + B hi/lo (2 x 32KB) = 128KB.
// ============================================================================
#define GT 256
#define AS_OFF(buf)  ((uint32_t)((buf) * 32768))
#define BS_OFF(hl)   ((uint32_t)(65536 + (hl) * 32768))
#define SM_TOTAL     131072

__device__ __forceinline__ void load_A_tile(uint32_t smem_base, int buf,
                                            int node0, int N, int tid) {
#pragma unroll
    for (int i = 0; i < 8; i++) {
        int idx  = tid + (i << 8);        // 0..2047 16B chunks
        int row  = idx >> 4;              // 0..127
        int cc   = idx & 15;              // chunk within row (8 fp16 each)
        int node = node0 + row;
        uint32_t sz    = (node < N) ? 16u : 0u;
        uint32_t chunk = (uint32_t)(cc ^ (row & 7));
        uint32_t doff  = (uint32_t)row * 256u + chunk * 16u;
        const __half* sh = g_xh + (size_t)node * D + cc * 8;
        CP_ASYNC16(smem_base + AS_OFF(buf) + doff, sh, sz);
    }
}

__global__ __launch_bounds__(GT, 1)
void gemm_kernel(const float* __restrict__ W,
                 const float* __restrict__ bias,
                 float* __restrict__ out,
                 int N) {
    extern __shared__ char smem[];
    uint32_t smem_base = smem_to_u32(smem);
    const int tid  = threadIdx.x;
    const int lane = tid & 31;
    const int wid  = tid >> 5;
    const int warp_m = (wid & 3) << 5;
    const int warp_n = (wid >> 2) << 6;

    const int num_tiles = (N + 127) >> 7;
    const int total = num_tiles * 2;
    int cur_nh = -1;

    int item = blockIdx.x;
    int buf = 0;
    if (item < total) load_A_tile(smem_base, 0, (item % num_tiles) << 7, N, tid);
    CP_COMMIT();

    for (; item < total; item += gridDim.x) {
        const int m_tile = item % num_tiles;
        const int nh     = item / num_tiles;
        const int node0  = m_tile << 7;

        int next = item + gridDim.x;
        if (next < total)
            load_A_tile(smem_base, buf ^ 1, (next % num_tiles) << 7, N, tid);
        CP_COMMIT();

        // (re)load B = W[nh*128 : +128][:] split into fp16 hi/lo
        if (nh != cur_nh) {
            cur_nh = nh;
#pragma unroll
            for (int j = 0; j < 32; j++) {
                int idx = tid + (j << 8);          // 0..8191 (half2 pairs)
                int k   = idx >> 6;                // 0..127
                int n   = (idx & 63) << 1;         // even col
                const float* wp = W + ((size_t)(nh * 128 + k)) * 128 + n;
                float w0 = wp[0], w1 = wp[1];
                __half2 h = __floats2half2_rn(w0, w1);
                float q0 = w0 - __half2float(__low2half(h));
                float q1 = w1 - __half2float(__high2half(h));
                __half2 l = __floats2half2_rn(q0, q1);
                uint32_t boff = (uint32_t)k * 256u
                              + (uint32_t)(((n >> 3) ^ (k & 7)) << 4)
                              + (uint32_t)((n & 7) << 1);
                *reinterpret_cast<uint32_t*>(smem + BS_OFF(0) + boff) = *(uint32_t*)&h;
                *reinterpret_cast<uint32_t*>(smem + BS_OFF(1) + boff) = *(uint32_t*)&l;
            }
        }

        CP_WAIT1();
        __syncthreads();     // A(buf) ready + B visible

        float acc[2][8][4];
#pragma unroll
        for (int mi = 0; mi < 2; mi++)
#pragma unroll
            for (int ni = 0; ni < 8; ni++)
#pragma unroll
                for (int q = 0; q < 4; q++) acc[mi][ni][q] = 0.f;

#pragma unroll
        for (int ks = 0; ks < 8; ks++) {
            uint32_t ah[2][4];
#pragma unroll
            for (int mi = 0; mi < 2; mi++) {
                int row = warp_m + (mi << 4) + (lane & 15);
                int cb  = (ks << 1) + (lane >> 4);
                uint32_t addr = smem_base + AS_OFF(buf)
                              + (uint32_t)row * 256u
                              + (uint32_t)((cb ^ (row & 7)) << 4);
                LDSM_X4(ah[mi][0], ah[mi][1], ah[mi][2], ah[mi][3], addr);
            }
            uint32_t bh[8][2], bl[8][2];
#pragma unroll
            for (int nj = 0; nj < 4; nj++) {
                int row = (ks << 4) + (lane & 15);
                int cb  = (warp_n >> 3) + (nj << 1) + (lane >> 4);
                uint32_t addr = smem_base + BS_OFF(0)
                              + (uint32_t)row * 256u
                              + (uint32_t)((cb ^ (row & 7)) << 4);
                LDSM_X4T(bh[2*nj][0], bh[2*nj][1], bh[2*nj+1][0], bh[2*nj+1][1], addr);
                LDSM_X4T(bl[2*nj][0], bl[2*nj][1], bl[2*nj+1][0], bl[2*nj+1][1],
                         addr + 32768u);
            }
#pragma unroll
            for (int mi = 0; mi < 2; mi++)
#pragma unroll
                for (int ni = 0; ni < 8; ni++) {
                    MMA16816F16(acc[mi][ni], ah[mi], bh[ni]);   // Ah*Bh
                    MMA16816F16(acc[mi][ni], ah[mi], bl[ni]);   // Ah*Bl
                }
        }

        // ---- epilogue ----
        if (nh == 0) {
#pragma unroll
            for (int ni = 0; ni < 8; ni++) {
                int col = warp_n + (ni << 3) + ((lane & 3) << 1);
                float b0 = bias[col], b1 = bias[col + 1];
#pragma unroll
                for (int mi = 0; mi < 2; mi++) {
                    int r = warp_m + (mi << 4) + (lane >> 2);
                    int node = node0 + r;
                    if (node < N) {
                        float2 v = make_float2(acc[mi][ni][0] + b0, acc[mi][ni][1] + b1);
                        *reinterpret_cast<float2*>(out + (size_t)node * D + col) = v;
                    }
                    int node2 = node + 8;
                    if (node2 < N) {
                        float2 v = make_float2(acc[mi][ni][2] + b0, acc[mi][ni][3] + b1);
                        *reinterpret_cast<float2*>(out + (size_t)node2 * D + col) = v;
                    }
                }
            }
        } else {
            // y -> fp16 (half the write traffic, half the scatter gather traffic)
#pragma unroll
            for (int ni = 0; ni < 8; ni++) {
                int col = warp_n + (ni << 3) + ((lane & 3) << 1);
#pragma unroll
                for (int mi = 0; mi < 2; mi++) {
                    int r = warp_m + (mi << 4) + (lane >> 2);
                    int node = node0 + r;
                    if (node < N) {
                        __half2 v = __floats2half2_rn(acc[mi][ni][0], acc[mi][ni][1]);
                        *reinterpret_cast<__half2*>(g_yh + (size_t)node * D + col) = v;
                    }
                    int node2 = node + 8;
                    if (node2 < N) {
                        __half2 v = __floats2half2_rn(acc[mi][ni][2], acc[mi][ni][3]);
                        *reinterpret_cast<__half2*>(g_yh + (size_t)node2 * D + col) = v;
                    }
                }
            }
        }
        __syncthreads();
        buf ^= 1;
    }
}

// ============================================================================
// Kernel 3: edge scatter (warp per edge — proven shape), fp16 gather:
//   out[dst] += val * y[src]  via red.global.add.v4.f32
//   y row is 256 B: each lane loads uint2 (4 halves) -> 4 floats -> RED.v4
// ============================================================================
__global__ void scatter_kernel(const int*   __restrict__ esrc,
                               const int*   __restrict__ edst,
                               const float* __restrict__ eval_,
                               float* __restrict__ out,
                               int E) {
    int warp = (blockIdx.x * blockDim.x + threadIdx.x) >> 5;
    int lane = threadIdx.x & 31;
    if (warp >= E) return;

    int   s = esrc[warp];
    int   d = edst[warp];
    float v = eval_[warp];

    uint2 w = reinterpret_cast<const uint2*>(g_yh)[(size_t)s * 32 + lane];
    __half2 p0 = *reinterpret_cast<__half2*>(&w.x);
    __half2 p1 = *reinterpret_cast<__half2*>(&w.y);
    float2 f0 = __half22float2(p0);
    float2 f1 = __half22float2(p1);

    float* p = out + (size_t)d * D + lane * 4;
    asm volatile("red.global.add.v4.f32 [%0], {%1, %2, %3, %4};"
                 :: "l"(p), "f"(f0.x * v), "f"(f0.y * v),
                    "f"(f1.x * v), "f"(f1.y * v)
                 : "memory");
}

// ============================================================================
// Launch
// ============================================================================
extern "C" void kernel_launch(void* const* d_in, const int* in_sizes, int n_in,
                              void* d_out, int out_size) {
    const float* x     = (const float*)d_in[0];
    const int*   esrc  = (const int*)  d_in[1];
    const int*   edst  = (const int*)  d_in[2];
    const float* eval_ = (const float*)d_in[3];
    const float* W     = (const float*)d_in[4];
    const float* bias  = (const float*)d_in[5];
    float*       out   = (float*)d_out;

    const int N = in_sizes[0] / D;     // 100000
    const int E = in_sizes[1];         // 1600000

    // 1) round x -> fp16
    {
        int n4 = N * (D / 4);
        convert_kernel<<<(n4 + 255) / 256, 256>>>(x, n4);
    }
    // 2) persistent GEMM: d_out = x@W1 + b ; g_yh = fp16(x@W2)
    {
        static bool attr_set = false;
        if (!attr_set) {
            cudaFuncSetAttribute(gemm_kernel,
                                 cudaFuncAttributeMaxDynamicSharedMemorySize,
                                 SM_TOTAL);
            attr_set = true;
        }
        gemm_kernel<<<148, GT, SM_TOTAL>>>(W, bias, out, N);
    }
    // 3) scatter-add edges into d_out (warp per edge)
    {
        int blocks = (E + 7) / 8;      // 8 warps (256 thr) per block
        scatter_kernel<<<blocks, 256>>>(esrc, edst, eval_, out, E);
    }
}